// round 2
// baseline (speedup 1.0000x reference)
#include <cuda_runtime.h>
#include <cuda_fp16.h>
#include <cstdint>

#define DI __device__ __forceinline__

// ===================== problem sizes =====================
#define BATCH 16384
#define DIN   1024
#define DH    4096
#define DOUT  1000
#define NP5   1024   /* padded N for layer 5 */

// ===================== scratch (device globals; no allocations allowed) ==
__device__ __align__(128) __half g_hX [BATCH * DIN];
__device__ __align__(128) __half g_hW1[DH * DIN];
__device__ __align__(128) __half g_hW2[(DH/4) * DH];
__device__ __align__(128) __half g_hW3[(DH/4) * (DH/4)];
__device__ __align__(128) __half g_hW4[(DH/8) * (DH/4)];
__device__ __align__(128) __half g_hW5[NP5 * (DH/8)];     /* zero-padded rows >= 1000 */
__device__ __align__(128) __half g_act1[BATCH * DH];
__device__ __align__(128) __half g_act2[BATCH * (DH/4)];
__device__ __align__(128) __half g_act3[BATCH * (DH/4)];
__device__ __align__(128) __half g_act4[BATCH * (DH/8)];

// ===================== PTX helpers (sm_100-base safe: no tcgen05) ========
DI uint32_t smem_u32(const void* p) {
    uint32_t a;
    asm("{ .reg .u64 t; cvta.to.shared.u64 t, %1; cvt.u32.u64 %0, t; }" : "=r"(a) : "l"(p));
    return a;
}
DI void cp_async16(uint32_t saddr, const void* gptr) {
    asm volatile("cp.async.cg.shared.global [%0], [%1], 16;" :: "r"(saddr), "l"(gptr));
}
#define CP_COMMIT() asm volatile("cp.async.commit_group;" ::: "memory")
#define CP_WAIT1()  asm volatile("cp.async.wait_group 1;"  ::: "memory")

DI void ldm_x4(uint32_t* d, uint32_t addr) {
    asm volatile("ldmatrix.sync.aligned.m8n8.x4.shared.b16 {%0,%1,%2,%3}, [%4];"
        : "=r"(d[0]), "=r"(d[1]), "=r"(d[2]), "=r"(d[3]) : "r"(addr));
}
DI void ldm_x2(uint32_t* d, uint32_t addr) {
    asm volatile("ldmatrix.sync.aligned.m8n8.x2.shared.b16 {%0,%1}, [%2];"
        : "=r"(d[0]), "=r"(d[1]) : "r"(addr));
}
DI void mma16816(float* c, const uint32_t* a, const uint32_t* b) {
    asm volatile("mma.sync.aligned.m16n8k16.row.col.f32.f16.f16.f32 "
        "{%0,%1,%2,%3}, {%4,%5,%6,%7}, {%8,%9}, {%0,%1,%2,%3};"
        : "+f"(c[0]), "+f"(c[1]), "+f"(c[2]), "+f"(c[3])
        : "r"(a[0]), "r"(a[1]), "r"(a[2]), "r"(a[3]), "r"(b[0]), "r"(b[1]));
}

// ===================== GEMM: C[M,N] = A[M,K] @ W[N,K]^T ==================
// CTA tile 128x128, K-chunk 64 halves (128B swizzled rows), 8 warps (2x4),
// warp tile 64x32, m16n8k16 fragments, double-buffered cp.async.
#define BM 128
#define BN 128
#define BK 64
#define BUF_BYTES 32768            /* 16KB A + 16KB B */
#define SMEM_BYTES (2 * BUF_BYTES + 128)

DI uint32_t sw_off(int r, int c) {    // row r, 16B-chunk c (0..7) in 128B row
    return (uint32_t)(r * 128 + ((c ^ (r & 7)) << 4));
}

DI void load_chunk(uint32_t sb, int buf,
                   const __half* __restrict__ A, const __half* __restrict__ W,
                   int K, int k0, int m0, int n0, int tid)
{
    const int r0 = tid >> 3, cb = tid & 7;
    const uint32_t sA = sb + (uint32_t)buf * BUF_BYTES;
    const uint32_t sB = sA + 16384;
    #pragma unroll
    for (int p = 0; p < 4; p++) {
        int r = p * 32 + r0;
        cp_async16(sA + sw_off(r, cb),
                   (const char*)(A + (size_t)(m0 + r) * K + k0) + cb * 16);
    }
    #pragma unroll
    for (int p = 0; p < 4; p++) {
        int r = p * 32 + r0;
        cp_async16(sB + sw_off(r, cb),
                   (const char*)(W + (size_t)(n0 + r) * K + k0) + cb * 16);
    }
}

template <bool RELU, bool HASBIAS, typename OutT>
__global__ void __launch_bounds__(256) gemm_mma(
    const __half* __restrict__ A,   // [M, K] row-major
    const __half* __restrict__ W,   // [Npad, K] row-major (w-128 exact)
    const float*  __restrict__ S,   // [N]
    const float*  __restrict__ Bv,  // [N] or null
    OutT*         __restrict__ O,   // [M, N]
    int N, int K, float pre, float post)
{
    extern __shared__ char smraw[];
    char* sm = (char*)(((uintptr_t)smraw + 127) & ~(uintptr_t)127);
    const uint32_t sb = smem_u32(sm);

    const int tid = threadIdx.x;
    const int l   = tid & 31;
    const int wid = tid >> 5;
    const int wm  = wid & 1;        // 2 warps along M
    const int wn  = wid >> 1;       // 4 warps along N
    const int m0  = blockIdx.x * BM;
    const int n0  = blockIdx.y * BN;

    const int gid = l >> 2, tig = l & 3;
    const int la7 = l & 7, q1 = (l >> 3) & 1, q2 = l >> 4;

    float c[4][4][4];
    #pragma unroll
    for (int i = 0; i < 4; i++)
        #pragma unroll
        for (int j = 0; j < 4; j++)
            #pragma unroll
            for (int e = 0; e < 4; e++) c[i][j][e] = 0.f;

    const int nch = K >> 6;

    load_chunk(sb, 0, A, W, K, 0,  m0, n0, tid); CP_COMMIT();
    load_chunk(sb, 1, A, W, K, BK, m0, n0, tid); CP_COMMIT();

    for (int i = 0; i < nch; i++) {
        CP_WAIT1();
        __syncthreads();
        const uint32_t sA = sb + (uint32_t)(i & 1) * BUF_BYTES;
        const uint32_t sB = sA + 16384;

        #pragma unroll
        for (int ks = 0; ks < 4; ks++) {
            uint32_t a[4][4], b[4][2];
            #pragma unroll
            for (int mt = 0; mt < 4; mt++) {
                int r = wm * 64 + mt * 16 + la7 + q1 * 8;
                ldm_x4(a[mt], sA + (uint32_t)(r * 128 + ((((ks << 1) | q2) ^ la7) << 4)));
            }
            #pragma unroll
            for (int nt = 0; nt < 4; nt++) {
                int r = wn * 32 + nt * 8 + la7;
                ldm_x2(b[nt], sB + (uint32_t)(r * 128 + ((((ks << 1) | q1) ^ la7) << 4)));
            }
            #pragma unroll
            for (int mt = 0; mt < 4; mt++)
                #pragma unroll
                for (int nt = 0; nt < 4; nt++)
                    mma16816(c[mt][nt], a[mt], b[nt]);
        }
        __syncthreads();
        if (i + 2 < nch) load_chunk(sb, i & 1, A, W, K, (i + 2) * BK, m0, n0, tid);
        CP_COMMIT();
    }

    // ---------------- epilogue ----------------
    #pragma unroll
    for (int nt = 0; nt < 4; nt++) {
        const int n = n0 + wn * 32 + nt * 8 + tig * 2;
        float s0 = 0.f, s1 = 0.f, bb0 = 0.f, bb1 = 0.f;
        if (n < N)     { s0 = S[n];     if (HASBIAS) bb0 = Bv[n]; }
        if (n + 1 < N) { s1 = S[n + 1]; if (HASBIAS) bb1 = Bv[n + 1]; }
        #pragma unroll
        for (int mt = 0; mt < 4; mt++) {
            #pragma unroll
            for (int h = 0; h < 2; h++) {
                const int m = m0 + wm * 64 + mt * 16 + gid + h * 8;
                float v0 = pre * s0 * c[mt][nt][h * 2 + 0] + bb0;
                float v1 = pre * s1 * c[mt][nt][h * 2 + 1] + bb1;
                if (RELU) { v0 = fmaxf(v0, 0.f); v1 = fmaxf(v1, 0.f); }
                v0 *= post; v1 *= post;
                if constexpr (sizeof(OutT) == 2) {
                    if (n + 1 < N)
                        *(__half2*)((__half*)O + (size_t)m * N + n) = __floats2half2_rn(v0, v1);
                    else if (n < N)
                        ((__half*)O)[(size_t)m * N + n] = __float2half_rn(v0);
                } else {
                    if (n + 1 < N)
                        *(float2*)((float*)O + (size_t)m * N + n) = make_float2(v0, v1);
                    else if (n < N)
                        ((float*)O)[(size_t)m * N + n] = v0;
                }
            }
        }
    }
}

// ===================== conversion kernels =====================
__global__ void k_cvt_x(const float* __restrict__ x, __half* __restrict__ o) {
    int i = blockIdx.x * 256 + threadIdx.x;
    float4 v = ((const float4*)x)[i];
    ((__half2*)o)[2 * i]     = __floats2half2_rn(v.x, v.y);
    ((__half2*)o)[2 * i + 1] = __floats2half2_rn(v.z, v.w);
}
__global__ void k_cvt_w(const int* __restrict__ w, __half* __restrict__ o) {
    int i = blockIdx.x * 256 + threadIdx.x;
    int4 v = ((const int4*)w)[i];
    ((__half2*)o)[2 * i]     = __floats2half2_rn((float)(v.x - 128), (float)(v.y - 128));
    ((__half2*)o)[2 * i + 1] = __floats2half2_rn((float)(v.z - 128), (float)(v.w - 128));
}
// W5: convert 1000x512 and zero-pad to 1024x512
__global__ void k_cvt_w5(const int* __restrict__ w, __half* __restrict__ o) {
    int i = blockIdx.x * 256 + threadIdx.x;   // group of 4 elements
    int base = i * 4;
    int n = base >> 9;                         // /512
    __half2 a = __floats2half2_rn(0.f, 0.f), b = a;
    if (n < DOUT) {
        int4 v = ((const int4*)w)[base >> 2];
        a = __floats2half2_rn((float)(v.x - 128), (float)(v.y - 128));
        b = __floats2half2_rn((float)(v.z - 128), (float)(v.w - 128));
    }
    ((__half2*)o)[2 * i]     = a;
    ((__half2*)o)[2 * i + 1] = b;
}

// ===================== log_softmax (in place on d_out) =====================
__global__ void k_logsoftmax(float* __restrict__ io, int N) {
    const int row = blockIdx.x;
    float* p = io + (size_t)row * N;
    const int tid = threadIdx.x;
    __shared__ float sh[8];

    float x[4];
    float mx = -3.4e38f;
    #pragma unroll
    for (int j = 0; j < 4; j++) {
        int c = tid + j * 256;
        x[j] = (c < N) ? p[c] : -3.4e38f;
        mx = fmaxf(mx, x[j]);
    }
    #pragma unroll
    for (int o = 16; o > 0; o >>= 1) mx = fmaxf(mx, __shfl_xor_sync(0xffffffffu, mx, o));
    if ((tid & 31) == 0) sh[tid >> 5] = mx;
    __syncthreads();
    float bm = sh[0];
    #pragma unroll
    for (int j = 1; j < 8; j++) bm = fmaxf(bm, sh[j]);

    float s = 0.f;
    #pragma unroll
    for (int j = 0; j < 4; j++) {
        int c = tid + j * 256;
        if (c < N) s += expf(x[j] - bm);
    }
    #pragma unroll
    for (int o = 16; o > 0; o >>= 1) s += __shfl_xor_sync(0xffffffffu, s, o);
    __syncthreads();
    if ((tid & 31) == 0) sh[tid >> 5] = s;
    __syncthreads();
    float bs = 0.f;
    #pragma unroll
    for (int j = 0; j < 8; j++) bs += sh[j];

    float L = bm + logf(bs);
    #pragma unroll
    for (int j = 0; j < 4; j++) {
        int c = tid + j * 256;
        if (c < N) p[c] = x[j] - L;
    }
}

// ===================== launcher =====================
extern "C" void kernel_launch(void* const* d_in, const int* in_sizes, int n_in,
                              void* d_out, int out_size)
{
    const float* X  = (const float*)d_in[0];
    const int*   w1 = (const int*)d_in[1];  const float* s1 = (const float*)d_in[2];  const float* b1 = (const float*)d_in[3];
    const int*   w2 = (const int*)d_in[4];  const float* s2 = (const float*)d_in[5];  const float* b2 = (const float*)d_in[6];
    const int*   w3 = (const int*)d_in[7];  const float* s3 = (const float*)d_in[8];  const float* b3 = (const float*)d_in[9];
    const int*   w4 = (const int*)d_in[10]; const float* s4 = (const float*)d_in[11]; const float* b4 = (const float*)d_in[12];
    const int*   w5 = (const int*)d_in[13]; const float* s5 = (const float*)d_in[14];
    float* out = (float*)d_out;

    void *hX, *hW1, *hW2, *hW3, *hW4, *hW5, *a1, *a2, *a3, *a4;
    cudaGetSymbolAddress(&hX,  g_hX);
    cudaGetSymbolAddress(&hW1, g_hW1);
    cudaGetSymbolAddress(&hW2, g_hW2);
    cudaGetSymbolAddress(&hW3, g_hW3);
    cudaGetSymbolAddress(&hW4, g_hW4);
    cudaGetSymbolAddress(&hW5, g_hW5);
    cudaGetSymbolAddress(&a1,  g_act1);
    cudaGetSymbolAddress(&a2,  g_act2);
    cudaGetSymbolAddress(&a3,  g_act3);
    cudaGetSymbolAddress(&a4,  g_act4);

    cudaFuncSetAttribute(gemm_mma<true,  true,  __half>,
                         cudaFuncAttributeMaxDynamicSharedMemorySize, SMEM_BYTES);
    cudaFuncSetAttribute(gemm_mma<false, false, float>,
                         cudaFuncAttributeMaxDynamicSharedMemorySize, SMEM_BYTES);

    // dtype conversions (weights: exact int -> fp16; X: fp32 -> fp16)
    k_cvt_x <<<(BATCH * DIN) / 1024, 256>>>(X, (__half*)hX);
    k_cvt_w <<<(DH * DIN) / 1024, 256>>>(w1, (__half*)hW1);
    k_cvt_w <<<((DH/4) * DH) / 1024, 256>>>(w2, (__half*)hW2);
    k_cvt_w <<<((DH/4) * (DH/4)) / 1024, 256>>>(w3, (__half*)hW3);
    k_cvt_w <<<((DH/8) * (DH/4)) / 1024, 256>>>(w4, (__half*)hW4);
    k_cvt_w5<<<(NP5 * (DH/8)) / 1024, 256>>>(w5, (__half*)hW5);

    // GEMM chain; act3 stored x2^-6, act4 stored x2^-9 (ReLU-homogeneous, exact)
    gemm_mma<true,  true,  __half><<<dim3(BATCH/BM, DH/BN),     256, SMEM_BYTES>>>(
        (const __half*)hX, (const __half*)hW1, s1, b1, (__half*)a1, DH,    DIN,  1.f,   1.f);
    gemm_mma<true,  true,  __half><<<dim3(BATCH/BM, (DH/4)/BN), 256, SMEM_BYTES>>>(
        (const __half*)a1, (const __half*)hW2, s2, b2, (__half*)a2, DH/4,  DH,   1.f,   1.f);
    gemm_mma<true,  true,  __half><<<dim3(BATCH/BM, (DH/4)/BN), 256, SMEM_BYTES>>>(
        (const __half*)a2, (const __half*)hW3, s3, b3, (__half*)a3, DH/4,  DH/4, 1.f,   0.015625f);
    gemm_mma<true,  true,  __half><<<dim3(BATCH/BM, (DH/8)/BN), 256, SMEM_BYTES>>>(
        (const __half*)a3, (const __half*)hW4, s4, b4, (__half*)a4, DH/8,  DH/4, 64.f,  0.001953125f);
    gemm_mma<false, false, float ><<<dim3(BATCH/BM, NP5/BN),    256, SMEM_BYTES>>>(
        (const __half*)a4, (const __half*)hW5, s5, nullptr, out,    DOUT,  DH/8, 512.f, 1.f);

    k_logsoftmax<<<BATCH, 256>>>(out, DOUT);
}

// round 4
// speedup vs baseline: 1.1203x; 1.1203x over previous
#include <cuda_runtime.h>
#include <cuda_fp16.h>
#include <cstdint>

#define DI __device__ __forceinline__

// ===================== problem sizes =====================
#define BATCH 16384
#define DIN   1024
#define DH    4096
#define DOUT  1000
#define NP5   1024   /* padded N for layer 5 */

// ===================== scratch (device globals; no allocations allowed) ==
__device__ __align__(128) __half g_hX [BATCH * DIN];
__device__ __align__(128) __half g_hW1[DH * DIN];
__device__ __align__(128) __half g_hW2[(DH/4) * DH];
__device__ __align__(128) __half g_hW3[(DH/4) * (DH/4)];
__device__ __align__(128) __half g_hW4[(DH/8) * (DH/4)];
__device__ __align__(128) __half g_hW5[NP5 * (DH/8)];     /* zero-padded rows >= 1000 */
__device__ __align__(128) __half g_act1[BATCH * DH];
__device__ __align__(128) __half g_act2[BATCH * (DH/4)];
__device__ __align__(128) __half g_act3[BATCH * (DH/4)];
__device__ __align__(128) __half g_act4[BATCH * (DH/8)];

// ===================== PTX helpers (sm_100-base safe: no tcgen05) ========
DI uint32_t smem_u32(const void* p) {
    uint32_t a;
    asm("{ .reg .u64 t; cvta.to.shared.u64 t, %1; cvt.u32.u64 %0, t; }" : "=r"(a) : "l"(p));
    return a;
}
DI void cp_async16(uint32_t saddr, const void* gptr) {
    asm volatile("cp.async.cg.shared.global [%0], [%1], 16;" :: "r"(saddr), "l"(gptr));
}
#define CP_COMMIT() asm volatile("cp.async.commit_group;" ::: "memory")
#define CP_WAIT1()  asm volatile("cp.async.wait_group 1;"  ::: "memory")

DI void ldm_x4(uint32_t* d, uint32_t addr) {
    asm volatile("ldmatrix.sync.aligned.m8n8.x4.shared.b16 {%0,%1,%2,%3}, [%4];"
        : "=r"(d[0]), "=r"(d[1]), "=r"(d[2]), "=r"(d[3]) : "r"(addr));
}
DI void mma16816(float* c, const uint32_t* a, const uint32_t* b) {
    asm volatile("mma.sync.aligned.m16n8k16.row.col.f32.f16.f16.f32 "
        "{%0,%1,%2,%3}, {%4,%5,%6,%7}, {%8,%9}, {%0,%1,%2,%3};"
        : "+f"(c[0]), "+f"(c[1]), "+f"(c[2]), "+f"(c[3])
        : "r"(a[0]), "r"(a[1]), "r"(a[2]), "r"(a[3]), "r"(b[0]), "r"(b[1]));
}

// ===================== GEMM: C[M,N] = A[M,K] @ W[N,K]^T ==================
// CTA tile 128x128, K-chunk 64 halves (128B swizzled rows), 8 warps (2x4),
// warp tile 64x32, m16n8k16 fragments, 3-stage cp.async ring, 2 CTA/SM.
#define BM 128
#define BN 128
#define BK 64
#define STAGES 3
#define BUF_BYTES 32768            /* 16KB A + 16KB B per stage */
#define SMEM_BYTES (STAGES * BUF_BYTES + 128)

DI uint32_t sw_off(int r, int c) {    // row r, 16B-chunk c (0..7) in 128B row
    return (uint32_t)(r * 128 + ((c ^ (r & 7)) << 4));
}

DI void load_chunk(uint32_t sb, int buf,
                   const __half* __restrict__ A, const __half* __restrict__ W,
                   int K, int k0, int m0, int n0, int tid)
{
    const int r0 = tid >> 3, cb = tid & 7;
    const uint32_t sA = sb + (uint32_t)buf * BUF_BYTES;
    const uint32_t sB = sA + 16384;
    #pragma unroll
    for (int p = 0; p < 4; p++) {
        int r = p * 32 + r0;
        cp_async16(sA + sw_off(r, cb),
                   (const char*)(A + (size_t)(m0 + r) * K + k0) + cb * 16);
    }
    #pragma unroll
    for (int p = 0; p < 4; p++) {
        int r = p * 32 + r0;
        cp_async16(sB + sw_off(r, cb),
                   (const char*)(W + (size_t)(n0 + r) * K + k0) + cb * 16);
    }
}

template <bool RELU, bool HASBIAS, typename OutT>
__global__ void __launch_bounds__(256, 2) gemm_mma(
    const __half* __restrict__ A,   // [M, K] row-major
    const __half* __restrict__ W,   // [Npad, K] row-major (w-128 exact)
    const float*  __restrict__ S,   // [N]
    const float*  __restrict__ Bv,  // [N] or null
    OutT*         __restrict__ O,   // [M, N]
    int N, int K, float pre, float post)
{
    extern __shared__ char smraw[];
    char* sm = (char*)(((uintptr_t)smraw + 127) & ~(uintptr_t)127);
    const uint32_t sb = smem_u32(sm);

    const int tid = threadIdx.x;
    const int l   = tid & 31;
    const int wid = tid >> 5;
    const int wm  = wid & 1;        // 2 warps along M
    const int wn  = wid >> 1;       // 4 warps along N
    const int m0  = blockIdx.x * BM;
    const int n0  = blockIdx.y * BN;

    const int gid = l >> 2, tig = l & 3;
    const int la7 = l & 7, q1 = (l >> 3) & 1, q2 = l >> 4;

    float c[4][4][4];
    #pragma unroll
    for (int i = 0; i < 4; i++)
        #pragma unroll
        for (int j = 0; j < 4; j++)
            #pragma unroll
            for (int e = 0; e < 4; e++) c[i][j][e] = 0.f;

    const int nch = K >> 6;

    load_chunk(sb, 0, A, W, K, 0,  m0, n0, tid); CP_COMMIT();
    load_chunk(sb, 1, A, W, K, BK, m0, n0, tid); CP_COMMIT();

    for (int i = 0; i < nch; i++) {
        CP_WAIT1();            // own group i complete (<=1 younger pending)
        __syncthreads();       // all threads' group i visible; ring slot (i+2)%3 free

        // prefetch stage i+2 into ring slot (i+2)%3 == (i-1)%3 (freed by the barrier)
        if (i + 2 < nch) load_chunk(sb, (i + 2) % STAGES, A, W, K, (i + 2) * BK, m0, n0, tid);
        CP_COMMIT();

        const uint32_t sA = sb + (uint32_t)(i % STAGES) * BUF_BYTES;
        const uint32_t sB = sA + 16384;

        #pragma unroll
        for (int ks = 0; ks < 4; ks++) {
            uint32_t a[4][4], b[4][2];
            #pragma unroll
            for (int mt = 0; mt < 4; mt++) {
                int r = wm * 64 + mt * 16 + la7 + q1 * 8;
                ldm_x4(a[mt], sA + (uint32_t)(r * 128 + ((((ks << 1) | q2) ^ la7) << 4)));
            }
            // B: one x4 per n-group pair: matrices (ng0,k0),(ng0,k1),(ng1,k0),(ng1,k1)
            #pragma unroll
            for (int p = 0; p < 2; p++) {
                uint32_t d[4];
                int r = wn * 32 + p * 16 + q2 * 8 + la7;
                ldm_x4(d, sB + (uint32_t)(r * 128 + ((((ks << 1) | q1) ^ la7) << 4)));
                b[2 * p][0] = d[0]; b[2 * p][1] = d[1];
                b[2 * p + 1][0] = d[2]; b[2 * p + 1][1] = d[3];
            }
            #pragma unroll
            for (int mt = 0; mt < 4; mt++)
                #pragma unroll
                for (int nt = 0; nt < 4; nt++)
                    mma16816(c[mt][nt], a[mt], b[nt]);
        }
    }

    // ---------------- epilogue ----------------
    #pragma unroll
    for (int nt = 0; nt < 4; nt++) {
        const int n = n0 + wn * 32 + nt * 8 + tig * 2;
        float s0 = 0.f, s1 = 0.f, bb0 = 0.f, bb1 = 0.f;
        if (n < N)     { s0 = S[n];     if (HASBIAS) bb0 = Bv[n]; }
        if (n + 1 < N) { s1 = S[n + 1]; if (HASBIAS) bb1 = Bv[n + 1]; }
        #pragma unroll
        for (int mt = 0; mt < 4; mt++) {
            #pragma unroll
            for (int h = 0; h < 2; h++) {
                const int m = m0 + wm * 64 + mt * 16 + gid + h * 8;
                float v0 = pre * s0 * c[mt][nt][h * 2 + 0] + bb0;
                float v1 = pre * s1 * c[mt][nt][h * 2 + 1] + bb1;
                if (RELU) { v0 = fmaxf(v0, 0.f); v1 = fmaxf(v1, 0.f); }
                v0 *= post; v1 *= post;
                if constexpr (sizeof(OutT) == 2) {
                    if (n + 1 < N)
                        *(__half2*)((__half*)O + (size_t)m * N + n) = __floats2half2_rn(v0, v1);
                    else if (n < N)
                        ((__half*)O)[(size_t)m * N + n] = __float2half_rn(v0);
                } else {
                    if (n + 1 < N)
                        *(float2*)((float*)O + (size_t)m * N + n) = make_float2(v0, v1);
                    else if (n < N)
                        ((float*)O)[(size_t)m * N + n] = v0;
                }
            }
        }
    }
}

// ===================== conversion kernels =====================
__global__ void k_cvt_x(const float* __restrict__ x, __half* __restrict__ o) {
    int i = blockIdx.x * 256 + threadIdx.x;
    float4 v = ((const float4*)x)[i];
    ((__half2*)o)[2 * i]     = __floats2half2_rn(v.x, v.y);
    ((__half2*)o)[2 * i + 1] = __floats2half2_rn(v.z, v.w);
}
__global__ void k_cvt_w(const int* __restrict__ w, __half* __restrict__ o) {
    int i = blockIdx.x * 256 + threadIdx.x;
    int4 v = ((const int4*)w)[i];
    ((__half2*)o)[2 * i]     = __floats2half2_rn((float)(v.x - 128), (float)(v.y - 128));
    ((__half2*)o)[2 * i + 1] = __floats2half2_rn((float)(v.z - 128), (float)(v.w - 128));
}
// W5: convert 1000x512 and zero-pad to 1024x512
__global__ void k_cvt_w5(const int* __restrict__ w, __half* __restrict__ o) {
    int i = blockIdx.x * 256 + threadIdx.x;   // group of 4 elements
    int base = i * 4;
    int n = base >> 9;                         // /512
    __half2 a = __floats2half2_rn(0.f, 0.f), b = a;
    if (n < DOUT) {
        int4 v = ((const int4*)w)[base >> 2];
        a = __floats2half2_rn((float)(v.x - 128), (float)(v.y - 128));
        b = __floats2half2_rn((float)(v.z - 128), (float)(v.w - 128));
    }
    ((__half2*)o)[2 * i]     = a;
    ((__half2*)o)[2 * i + 1] = b;
}

// ===================== log_softmax (in place on d_out) =====================
__global__ void k_logsoftmax(float* __restrict__ io, int N) {
    const int row = blockIdx.x;
    float* p = io + (size_t)row * N;
    const int tid = threadIdx.x;
    __shared__ float sh[8];

    float x[4];
    float mx = -3.4e38f;
    #pragma unroll
    for (int j = 0; j < 4; j++) {
        int c = tid + j * 256;
        x[j] = (c < N) ? p[c] : -3.4e38f;
        mx = fmaxf(mx, x[j]);
    }
    #pragma unroll
    for (int o = 16; o > 0; o >>= 1) mx = fmaxf(mx, __shfl_xor_sync(0xffffffffu, mx, o));
    if ((tid & 31) == 0) sh[tid >> 5] = mx;
    __syncthreads();
    float bm = sh[0];
    #pragma unroll
    for (int j = 1; j < 8; j++) bm = fmaxf(bm, sh[j]);

    float s = 0.f;
    #pragma unroll
    for (int j = 0; j < 4; j++) {
        int c = tid + j * 256;
        if (c < N) s += expf(x[j] - bm);
    }
    #pragma unroll
    for (int o = 16; o > 0; o >>= 1) s += __shfl_xor_sync(0xffffffffu, s, o);
    __syncthreads();
    if ((tid & 31) == 0) sh[tid >> 5] = s;
    __syncthreads();
    float bs = 0.f;
    #pragma unroll
    for (int j = 0; j < 8; j++) bs += sh[j];

    float L = bm + logf(bs);
    #pragma unroll
    for (int j = 0; j < 4; j++) {
        int c = tid + j * 256;
        if (c < N) p[c] = x[j] - L;
    }
}

// ===================== launcher =====================
extern "C" void kernel_launch(void* const* d_in, const int* in_sizes, int n_in,
                              void* d_out, int out_size)
{
    const float* X  = (const float*)d_in[0];
    const int*   w1 = (const int*)d_in[1];  const float* s1 = (const float*)d_in[2];  const float* b1 = (const float*)d_in[3];
    const int*   w2 = (const int*)d_in[4];  const float* s2 = (const float*)d_in[5];  const float* b2 = (const float*)d_in[6];
    const int*   w3 = (const int*)d_in[7];  const float* s3 = (const float*)d_in[8];  const float* b3 = (const float*)d_in[9];
    const int*   w4 = (const int*)d_in[10]; const float* s4 = (const float*)d_in[11]; const float* b4 = (const float*)d_in[12];
    const int*   w5 = (const int*)d_in[13]; const float* s5 = (const float*)d_in[14];
    float* out = (float*)d_out;

    void *hX, *hW1, *hW2, *hW3, *hW4, *hW5, *a1, *a2, *a3, *a4;
    cudaGetSymbolAddress(&hX,  g_hX);
    cudaGetSymbolAddress(&hW1, g_hW1);
    cudaGetSymbolAddress(&hW2, g_hW2);
    cudaGetSymbolAddress(&hW3, g_hW3);
    cudaGetSymbolAddress(&hW4, g_hW4);
    cudaGetSymbolAddress(&hW5, g_hW5);
    cudaGetSymbolAddress(&a1,  g_act1);
    cudaGetSymbolAddress(&a2,  g_act2);
    cudaGetSymbolAddress(&a3,  g_act3);
    cudaGetSymbolAddress(&a4,  g_act4);

    cudaFuncSetAttribute(gemm_mma<true,  true,  __half>,
                         cudaFuncAttributeMaxDynamicSharedMemorySize, SMEM_BYTES);
    cudaFuncSetAttribute(gemm_mma<false, false, float>,
                         cudaFuncAttributeMaxDynamicSharedMemorySize, SMEM_BYTES);

    // dtype conversions (weights: exact int -> fp16; X: fp32 -> fp16)
    k_cvt_x <<<(BATCH * DIN) / 1024, 256>>>(X, (__half*)hX);
    k_cvt_w <<<(DH * DIN) / 1024, 256>>>(w1, (__half*)hW1);
    k_cvt_w <<<((DH/4) * DH) / 1024, 256>>>(w2, (__half*)hW2);
    k_cvt_w <<<((DH/4) * (DH/4)) / 1024, 256>>>(w3, (__half*)hW3);
    k_cvt_w <<<((DH/8) * (DH/4)) / 1024, 256>>>(w4, (__half*)hW4);
    k_cvt_w5<<<(NP5 * (DH/8)) / 1024, 256>>>(w5, (__half*)hW5);

    // GEMM chain; act3 stored x2^-6, act4 stored x2^-9 (ReLU-homogeneous, exact)
    gemm_mma<true,  true,  __half><<<dim3(BATCH/BM, DH/BN),     256, SMEM_BYTES>>>(
        (const __half*)hX, (const __half*)hW1, s1, b1, (__half*)a1, DH,    DIN,  1.f,   1.f);
    gemm_mma<true,  true,  __half><<<dim3(BATCH/BM, (DH/4)/BN), 256, SMEM_BYTES>>>(
        (const __half*)a1, (const __half*)hW2, s2, b2, (__half*)a2, DH/4,  DH,   1.f,   1.f);
    gemm_mma<true,  true,  __half><<<dim3(BATCH/BM, (DH/4)/BN), 256, SMEM_BYTES>>>(
        (const __half*)a2, (const __half*)hW3, s3, b3, (__half*)a3, DH/4,  DH/4, 1.f,   0.015625f);
    gemm_mma<true,  true,  __half><<<dim3(BATCH/BM, (DH/8)/BN), 256, SMEM_BYTES>>>(
        (const __half*)a3, (const __half*)hW4, s4, b4, (__half*)a4, DH/8,  DH/4, 64.f,  0.001953125f);
    gemm_mma<false, false, float ><<<dim3(BATCH/BM, NP5/BN),    256, SMEM_BYTES>>>(
        (const __half*)a4, (const __half*)hW5, s5, nullptr, out,    DOUT,  DH/8, 512.f, 1.f);

    k_logsoftmax<<<BATCH, 256>>>(out, DOUT);
}